// round 3
// baseline (speedup 1.0000x reference)
#include <cuda_runtime.h>
#include <cstdint>

#define B_GR   8192
#define NPG    39
#define N_TOT  (B_GR*NPG)
#define DEG    8
#define EPG    (NPG*DEG)          /* 312 */
#define E_TOT  (N_TOT*DEG)        /* 2555904 */
#define TE     (EPG+NPG)          /* 351 edges incl self loops */
#define FDIM   4560

// ---------------- scratch (static device globals: no runtime alloc) -------
__device__ float g_f [(size_t)B_GR*FDIM];   // 149 MB
__device__ float g_h1[(size_t)B_GR*1024];
__device__ float g_h2[(size_t)B_GR*128];
__device__ int   g_is64;

// ---------------- edge dtype detection ------------------------------------
// int64 little-endian: all high words of non-negative values < 2^31 are 0.
// int32: odd words are graph-0 src ids uniform in [0,39) -> ~never all zero.
__global__ void detect_kernel(const unsigned* __restrict__ e) {
    int any = __syncthreads_or(e[2*threadIdx.x + 1] != 0u);
    if (threadIdx.x == 0) g_is64 = any ? 0 : 1;
}

// ---------------- fused 4-layer GAT, one CTA per graph --------------------
template<int Fi, int Fo>
__device__ __forceinline__ void gat_layer_dev(
    int g, int tid,
    float* hA, float* hB, float* wS, float* aSs, float* aDs, float* biasS,
    float* sN, float* dN, float* den, float* eV,
    const unsigned char* esrc, const unsigned char* edst,
    const unsigned short* order, const int* startS,
    const float* __restrict__ W, const float* __restrict__ a_s,
    const float* __restrict__ a_d, const float* __restrict__ bvec,
    float* __restrict__ f, int resOff, int poolOff)
{
    // stage weights
    for (int i = tid; i < Fi*Fo; i += 256) wS[i] = W[i];
    if (tid < Fo) { aSs[tid] = a_s[tid]; aDs[tid] = a_d[tid]; biasS[tid] = bvec[tid]; }
    __syncthreads();

    // h = x @ W  (hA[n*Fi+ci] -> hB[n*Fo+c])
    if (Fo % 4 == 0) {
        for (int t = tid; t < NPG*(Fo/4); t += 256) {
            int n = t / (Fo/4), c4 = (t % (Fo/4)) * 4;
            float4 acc = make_float4(0.f,0.f,0.f,0.f);
            #pragma unroll
            for (int ci = 0; ci < Fi; ci++) {
                float a = hA[n*Fi + ci];
                const float4 w = *(const float4*)&wS[ci*Fo + c4];
                acc.x = fmaf(a, w.x, acc.x); acc.y = fmaf(a, w.y, acc.y);
                acc.z = fmaf(a, w.z, acc.z); acc.w = fmaf(a, w.w, acc.w);
            }
            *(float4*)&hB[n*Fo + c4] = acc;
        }
    } else {
        for (int t = tid; t < NPG*Fo; t += 256) {
            int n = t / Fo, c = t % Fo;
            float acc = 0.f;
            #pragma unroll
            for (int ci = 0; ci < Fi; ci++) acc = fmaf(hA[n*Fi + ci], wS[ci*Fo + c], acc);
            hB[t] = acc;
        }
    }
    __syncthreads();

    // per-node attention logits
    if (tid < NPG) {
        float s = 0.f, d = 0.f;
        #pragma unroll
        for (int c = 0; c < Fo; c++) { float h = hB[tid*Fo + c]; s = fmaf(h, aSs[c], s); d = fmaf(h, aDs[c], d); }
        sN[tid] = s; dN[tid] = d;
    }
    __syncthreads();

    // e_ij = LeakyReLU(s[src] + d[dst])
    for (int i = tid; i < TE; i += 256) {
        float e = sN[esrc[i]] + dN[edst[i]];
        eV[i] = (e > 0.f) ? e : 0.2f * e;
    }
    __syncthreads();

    // per-dst softmax stats via CSR (every dst has a self loop -> non-empty)
    if (tid < NPG) {
        int s0 = startS[tid], s1 = startS[tid+1];
        float m = -3.0e38f;
        for (int j = s0; j < s1; j++) m = fmaxf(m, eV[order[j]]);
        float dd = 0.f;
        for (int j = s0; j < s1; j++) { int i = order[j]; float w = expf(eV[i] - m); eV[i] = w; dd += w; }
        den[tid] = dd;
    }
    __syncthreads();

    // out[dst] = (sum_j w * h[src]) / (den+1e-16) + b, relu. Overwrite hA.
    long fb = (long)g*FDIM + resOff;
    if (Fo % 4 == 0) {
        for (int t = tid; t < NPG*(Fo/4); t += 256) {
            int d = t / (Fo/4), c4 = (t % (Fo/4)) * 4;
            int s0 = startS[d], s1 = startS[d+1];
            float4 acc = make_float4(0.f,0.f,0.f,0.f);
            for (int j = s0; j < s1; j++) {
                int i = order[j]; float w = eV[i];
                const float4 h = *(const float4*)&hB[(int)esrc[i]*Fo + c4];
                acc.x = fmaf(w, h.x, acc.x); acc.y = fmaf(w, h.y, acc.y);
                acc.z = fmaf(w, h.z, acc.z); acc.w = fmaf(w, h.w, acc.w);
            }
            float inv = 1.0f / (den[d] + 1e-16f);
            float o0 = fmaxf(acc.x*inv + biasS[c4+0], 0.f);
            float o1 = fmaxf(acc.y*inv + biasS[c4+1], 0.f);
            float o2 = fmaxf(acc.z*inv + biasS[c4+2], 0.f);
            float o3 = fmaxf(acc.w*inv + biasS[c4+3], 0.f);
            hA[d*Fo+c4+0]=o0; hA[d*Fo+c4+1]=o1; hA[d*Fo+c4+2]=o2; hA[d*Fo+c4+3]=o3;
            f[fb + d*Fo + c4+0]=o0; f[fb + d*Fo + c4+1]=o1;
            f[fb + d*Fo + c4+2]=o2; f[fb + d*Fo + c4+3]=o3;
        }
    } else {
        for (int t = tid; t < NPG*Fo; t += 256) {
            int d = t / Fo, c = t % Fo;
            int s0 = startS[d], s1 = startS[d+1];
            float acc = 0.f;
            for (int j = s0; j < s1; j++) { int i = order[j]; acc = fmaf(eV[i], hB[(int)esrc[i]*Fo + c], acc); }
            float o = fmaxf(acc / (den[d] + 1e-16f) + biasS[c], 0.f);
            hA[d*Fo + c] = o;
            f[fb + d*Fo + c] = o;
        }
    }
    __syncthreads();

    // graph max-pool of relu'd output
    if (tid < Fo) {
        float m = hA[tid];
        for (int n = 1; n < NPG; n++) m = fmaxf(m, hA[n*Fo + tid]);
        f[(long)g*FDIM + poolOff + tid] = m;
    }
    __syncthreads();
}

__global__ __launch_bounds__(256) void gat_kernel(
    const float* __restrict__ x, const void* __restrict__ edges,
    const float* __restrict__ W1, const float* __restrict__ as1, const float* __restrict__ ad1, const float* __restrict__ b1,
    const float* __restrict__ W2, const float* __restrict__ as2, const float* __restrict__ ad2, const float* __restrict__ b2,
    const float* __restrict__ W3, const float* __restrict__ as3, const float* __restrict__ ad3, const float* __restrict__ b3,
    const float* __restrict__ W4, const float* __restrict__ as4, const float* __restrict__ ad4, const float* __restrict__ b4,
    float* __restrict__ f)
{
    __shared__ float hA[NPG*64];
    __shared__ float hB[NPG*64];
    __shared__ float wS[64*32];
    __shared__ float aSs[64], aDs[64], biasS[64];
    __shared__ float sN[NPG], dN[NPG], den[NPG];
    __shared__ float eV[TE];
    __shared__ unsigned char  esrc[TE], edst[TE];
    __shared__ unsigned short order[TE];
    __shared__ int startS[NPG+1];
    __shared__ int cnt[NPG];

    const int g   = blockIdx.x;
    const int tid = threadIdx.x;
    const int is64 = g_is64;
    const long ebase = (long)g * EPG;

    // load x, write res0 slice
    if (tid < NPG) {
        float v = x[g*NPG + tid];
        hA[tid] = v;
        f[(long)g*FDIM + tid] = v;
    }
    // load edges -> local ids (graph-local, contiguous block per graph)
    for (int i = tid; i < EPG; i += 256) {
        int s, d;
        if (is64) {
            const long long* e = (const long long*)edges;
            s = (int)e[ebase + i]; d = (int)e[(long)E_TOT + ebase + i];
        } else {
            const int* e = (const int*)edges;
            s = e[ebase + i]; d = e[(long)E_TOT + ebase + i];
        }
        esrc[i] = (unsigned char)(s - g*NPG);
        edst[i] = (unsigned char)(d - g*NPG);
    }
    for (int i = EPG + tid; i < TE; i += 256) { esrc[i] = edst[i] = (unsigned char)(i - EPG); }
    if (tid < NPG) cnt[tid] = 0;
    __syncthreads();

    if (tid == 0) {          // pool of raw x (out0)
        float m = hA[0];
        for (int n = 1; n < NPG; n++) m = fmaxf(m, hA[n]);
        f[(long)g*FDIM + 4446] = m;
    }
    // CSR by dst (built once; structure shared across all 4 layers)
    for (int i = tid; i < TE; i += 256) atomicAdd(&cnt[edst[i]], 1);
    __syncthreads();
    if (tid == 0) {
        int run = 0;
        for (int d = 0; d < NPG; d++) { int c = cnt[d]; startS[d] = run; cnt[d] = run; run += c; }
        startS[NPG] = run;
    }
    __syncthreads();
    for (int i = tid; i < TE; i += 256) {
        int pos = atomicAdd(&cnt[edst[i]], 1);
        order[pos] = (unsigned short)i;
    }
    __syncthreads();

    gat_layer_dev<1, 8 >(g, tid, hA, hB, wS, aSs, aDs, biasS, sN, dN, den, eV, esrc, edst, order, startS, W1, as1, ad1, b1, f,   39, 4447);
    gat_layer_dev<8, 64>(g, tid, hA, hB, wS, aSs, aDs, biasS, sN, dN, den, eV, esrc, edst, order, startS, W2, as2, ad2, b2, f,  351, 4455);
    gat_layer_dev<64,32>(g, tid, hA, hB, wS, aSs, aDs, biasS, sN, dN, den, eV, esrc, edst, order, startS, W3, as3, ad3, b3, f, 2847, 4519);
    gat_layer_dev<32, 9>(g, tid, hA, hB, wS, aSs, aDs, biasS, sN, dN, den, eV, esrc, edst, order, startS, W4, as4, ad4, b4, f, 4095, 4551);
}

// ---------------- tiled fp32 SGEMM, C = act(A @ B + bias) -----------------
template<int BM, int BN, int BK, int TM, int TN, bool RELU>
__global__ __launch_bounds__((BM/TM)*(BN/TN)) void sgemm_kernel(
    int M, int Nn, int K,
    const float* __restrict__ A, const float* __restrict__ B,
    const float* __restrict__ bias, float* __restrict__ C)
{
    constexpr int THREADS = (BM/TM)*(BN/TN);
    __shared__ float As[2][BK][BM];
    __shared__ float Bs[2][BK][BN];

    const int brow = blockIdx.y, bcol = blockIdx.x;
    const int tid = threadIdx.x;
    const int tx = tid % (BN/TN);
    const int ty = tid / (BN/TN);

    const float* Ab = A + (long)brow*BM*K;
    const float* Bb = B + bcol*BN;

    constexpr int A_IT = (BM*BK/4) / THREADS;
    constexpr int B_IT = (BK*BN/4) / THREADS;
    static_assert((BM*BK/4) % THREADS == 0 && (BK*BN/4) % THREADS == 0, "tile/threads mismatch");

    float acc[TM][TN] = {};
    float4 aReg[A_IT], bReg[B_IT];

    auto loadGlobal = [&](int kt) {
        #pragma unroll
        for (int it = 0; it < A_IT; it++) {
            int fidx = tid + it*THREADS;
            int r = fidx / (BK/4), c = (fidx % (BK/4)) * 4;
            aReg[it] = *(const float4*)&Ab[(long)r*K + kt*BK + c];
        }
        #pragma unroll
        for (int it = 0; it < B_IT; it++) {
            int fidx = tid + it*THREADS;
            int r = fidx / (BN/4), c = (fidx % (BN/4)) * 4;
            bReg[it] = *(const float4*)&Bb[(long)(kt*BK + r)*Nn + c];
        }
    };
    auto storeSmem = [&](int buf) {
        #pragma unroll
        for (int it = 0; it < A_IT; it++) {
            int fidx = tid + it*THREADS;
            int r = fidx / (BK/4), c = (fidx % (BK/4)) * 4;
            As[buf][c+0][r] = aReg[it].x; As[buf][c+1][r] = aReg[it].y;
            As[buf][c+2][r] = aReg[it].z; As[buf][c+3][r] = aReg[it].w;
        }
        #pragma unroll
        for (int it = 0; it < B_IT; it++) {
            int fidx = tid + it*THREADS;
            int r = fidx / (BN/4), c = (fidx % (BN/4)) * 4;
            *(float4*)&Bs[buf][r][c] = bReg[it];
        }
    };

    const int nTiles = K / BK;
    loadGlobal(0);
    storeSmem(0);
    __syncthreads();

    for (int t = 0; t < nTiles; t++) {
        int cur = t & 1;
        if (t + 1 < nTiles) loadGlobal(t + 1);
        #pragma unroll
        for (int kk = 0; kk < BK; kk++) {
            float ra[TM], rb[TN];
            #pragma unroll
            for (int i = 0; i < TM; i++) ra[i] = As[cur][kk][ty*TM + i];
            #pragma unroll
            for (int j = 0; j < TN; j++) rb[j] = Bs[cur][kk][tx*TN + j];
            #pragma unroll
            for (int i = 0; i < TM; i++)
                #pragma unroll
                for (int j = 0; j < TN; j++)
                    acc[i][j] = fmaf(ra[i], rb[j], acc[i][j]);
        }
        if (t + 1 < nTiles) storeSmem((t + 1) & 1);
        __syncthreads();
    }

    #pragma unroll
    for (int i = 0; i < TM; i++) {
        long r = (long)brow*BM + ty*TM + i;
        #pragma unroll
        for (int j = 0; j < TN; j += 4) {
            int c = bcol*BN + tx*TN + j;
            float4 v;
            v.x = acc[i][j+0] + bias[c+0];
            v.y = acc[i][j+1] + bias[c+1];
            v.z = acc[i][j+2] + bias[c+2];
            v.w = acc[i][j+3] + bias[c+3];
            if (RELU) {
                v.x = fmaxf(v.x, 0.f); v.y = fmaxf(v.y, 0.f);
                v.z = fmaxf(v.z, 0.f); v.w = fmaxf(v.w, 0.f);
            }
            *(float4*)&C[r*Nn + c] = v;
        }
    }
}

// ---------------- tiny final GEMM [8192,128]x[128,9] ----------------------
__global__ void gemm3_kernel(const float* __restrict__ A, const float* __restrict__ W,
                             const float* __restrict__ bias, float* __restrict__ C)
{
    int idx = blockIdx.x*blockDim.x + threadIdx.x;
    if (idx >= B_GR*9) return;
    int r = idx / 9, c = idx % 9;
    const float* a = A + (long)r*128;
    float acc = bias[c];
    #pragma unroll 8
    for (int k = 0; k < 128; k++) acc = fmaf(a[k], W[k*9 + c], acc);
    C[idx] = acc;
}

// ---------------- launcher -------------------------------------------------
extern "C" void kernel_launch(void* const* d_in, const int* in_sizes, int n_in,
                              void* d_out, int out_size)
{
    (void)in_sizes; (void)n_in; (void)out_size;
    float *fbuf, *h1, *h2;
    cudaGetSymbolAddress((void**)&fbuf, g_f);
    cudaGetSymbolAddress((void**)&h1,  g_h1);
    cudaGetSymbolAddress((void**)&h2,  g_h2);

    detect_kernel<<<1, 128>>>((const unsigned*)d_in[1]);

    gat_kernel<<<B_GR, 256>>>(
        (const float*)d_in[0], d_in[1],
        (const float*)d_in[3],  (const float*)d_in[4],  (const float*)d_in[5],  (const float*)d_in[6],
        (const float*)d_in[7],  (const float*)d_in[8],  (const float*)d_in[9],  (const float*)d_in[10],
        (const float*)d_in[11], (const float*)d_in[12], (const float*)d_in[13], (const float*)d_in[14],
        (const float*)d_in[15], (const float*)d_in[16], (const float*)d_in[17], (const float*)d_in[18],
        fbuf);

    // f[8192,4560] @ lw1[4560,1024] + lb1, relu
    sgemm_kernel<128,128,16,8,8,true><<<dim3(1024/128, B_GR/128), 256>>>(
        B_GR, 1024, FDIM, fbuf, (const float*)d_in[19], (const float*)d_in[20], h1);
    // h1 @ lw2[1024,128] + lb2, relu
    sgemm_kernel<64,64,16,4,4,true><<<dim3(128/64, B_GR/64), 256>>>(
        B_GR, 128, 1024, h1, (const float*)d_in[21], (const float*)d_in[22], h2);
    // h2 @ lw3[128,9] + lb3
    gemm3_kernel<<<(B_GR*9 + 255)/256, 256>>>(
        h2, (const float*)d_in[23], (const float*)d_in[24], (float*)d_out);
}

// round 6
// speedup vs baseline: 1.8981x; 1.8981x over previous
#include <cuda_runtime.h>
#include <cuda_bf16.h>
#include <cstdint>

#define B_GR   8192
#define NPG    39
#define N_TOT  (B_GR*NPG)
#define DEG    8
#define EPG    (NPG*DEG)          /* 312 */
#define E_TOT  (N_TOT*DEG)        /* 2555904 */
#define TE     (EPG+NPG)          /* 351 */
#define FDIM   4560
#define KPAD   4608               /* FDIM padded to multiple of 32 */

// ---------------- scratch (static device globals, zero-initialized) -------
__device__ __nv_bfloat16 g_fh [(size_t)B_GR*KPAD];   // f hi   (pad cols stay 0)
__device__ __nv_bfloat16 g_fl [(size_t)B_GR*KPAD];   // f lo
__device__ __nv_bfloat16 g_bth[(size_t)1024*KPAD];   // lw1^T hi, K-major
__device__ __nv_bfloat16 g_btl[(size_t)1024*KPAD];   // lw1^T lo
__device__ float g_h1[(size_t)B_GR*1024];
__device__ float g_h2[(size_t)B_GR*128];
__device__ int   g_is64;

// ---------------- PTX helpers (baseline PTX only: sm_80-class) ------------
__device__ __forceinline__ uint32_t smem_u32(const void* p) {
    uint32_t a;
    asm("{ .reg .u64 t; cvta.to.shared.u64 t, %1; cvt.u32.u64 %0, t; }" : "=r"(a) : "l"(p));
    return a;
}
#define CP_ASYNC16(sa, ga) \
    asm volatile("cp.async.cg.shared.global [%0], [%1], 16;" :: "r"(sa), "l"(ga))
#define CP_COMMIT()  asm volatile("cp.async.commit_group;" ::: "memory")
#define CP_WAIT(n)   asm volatile("cp.async.wait_group %0;" :: "n"(n) : "memory")

#define LDSM4(r, addr) \
    asm volatile("ldmatrix.sync.aligned.m8n8.x4.shared.b16 {%0,%1,%2,%3}, [%4];" \
        : "=r"((r)[0]), "=r"((r)[1]), "=r"((r)[2]), "=r"((r)[3]) : "r"(addr))

#define MMA_BF16(acc, a, b) \
    asm volatile("mma.sync.aligned.m16n8k16.row.col.f32.bf16.bf16.f32 " \
        "{%0,%1,%2,%3}, {%4,%5,%6,%7}, {%8,%9}, {%0,%1,%2,%3};" \
        : "+f"((acc)[0]), "+f"((acc)[1]), "+f"((acc)[2]), "+f"((acc)[3]) \
        : "r"((a)[0]), "r"((a)[1]), "r"((a)[2]), "r"((a)[3]), \
          "r"((b)[0]), "r"((b)[1]))

__device__ __forceinline__ void put2(__nv_bfloat16* fh, __nv_bfloat16* fl, size_t idx, float v) {
    __nv_bfloat16 h = __float2bfloat16(v);
    fh[idx] = h;
    fl[idx] = __float2bfloat16(v - __bfloat162float(h));
}

// ---------------- edge dtype detection ------------------------------------
__global__ void detect_kernel(const unsigned* __restrict__ e) {
    int any = __syncthreads_or(e[2*threadIdx.x + 1] != 0u);
    if (threadIdx.x == 0) g_is64 = any ? 0 : 1;
}

// ---------------- transpose + split lw1 [4560,1024] -> [1024,4608] hi/lo --
__global__ __launch_bounds__(256) void tsplit_kernel(const float* __restrict__ W,
                                                     __nv_bfloat16* __restrict__ bh,
                                                     __nv_bfloat16* __restrict__ bl) {
    __shared__ float tile[32][33];
    int kb = blockIdx.y * 32, nb = blockIdx.x * 32;
    int tx = threadIdx.x, ty = threadIdx.y;       // (32,8)
    for (int i = ty; i < 32; i += 8) {
        int k = kb + i;
        tile[i][tx] = (k < FDIM) ? W[(size_t)k*1024 + nb + tx] : 0.f;
    }
    __syncthreads();
    for (int i = ty; i < 32; i += 8) {
        int n = nb + i, k = kb + tx;
        if (k < FDIM) put2(bh, bl, (size_t)n*KPAD + k, tile[tx][i]);
    }
}

// ---------------- fused 4-layer GAT, one CTA per graph --------------------
template<int Fi, int Fo>
__device__ __forceinline__ void gat_layer_dev(
    int g, int tid,
    float* hA, float* hB, float* wS, float* aSs, float* aDs, float* biasS,
    float* sN, float* dN, float* den, float* eV,
    const unsigned char* esrc, const unsigned char* edst,
    const unsigned short* order, const int* startS,
    const float* __restrict__ W, const float* __restrict__ a_s,
    const float* __restrict__ a_d, const float* __restrict__ bvec,
    __nv_bfloat16* __restrict__ fh, __nv_bfloat16* __restrict__ fl,
    int resOff, int poolOff)
{
    for (int i = tid; i < Fi*Fo; i += 256) wS[i] = W[i];
    if (tid < Fo) { aSs[tid] = a_s[tid]; aDs[tid] = a_d[tid]; biasS[tid] = bvec[tid]; }
    __syncthreads();

    if (Fo % 4 == 0) {
        for (int t = tid; t < NPG*(Fo/4); t += 256) {
            int n = t / (Fo/4), c4 = (t % (Fo/4)) * 4;
            float4 acc = make_float4(0.f,0.f,0.f,0.f);
            #pragma unroll
            for (int ci = 0; ci < Fi; ci++) {
                float a = hA[n*Fi + ci];
                const float4 w = *(const float4*)&wS[ci*Fo + c4];
                acc.x = fmaf(a, w.x, acc.x); acc.y = fmaf(a, w.y, acc.y);
                acc.z = fmaf(a, w.z, acc.z); acc.w = fmaf(a, w.w, acc.w);
            }
            *(float4*)&hB[n*Fo + c4] = acc;
        }
    } else {
        for (int t = tid; t < NPG*Fo; t += 256) {
            int n = t / Fo, c = t % Fo;
            float acc = 0.f;
            #pragma unroll
            for (int ci = 0; ci < Fi; ci++) acc = fmaf(hA[n*Fi + ci], wS[ci*Fo + c], acc);
            hB[t] = acc;
        }
    }
    __syncthreads();

    if (tid < NPG) {
        float s = 0.f, d = 0.f;
        #pragma unroll
        for (int c = 0; c < Fo; c++) { float h = hB[tid*Fo + c]; s = fmaf(h, aSs[c], s); d = fmaf(h, aDs[c], d); }
        sN[tid] = s; dN[tid] = d;
    }
    __syncthreads();

    for (int i = tid; i < TE; i += 256) {
        float e = sN[esrc[i]] + dN[edst[i]];
        eV[i] = (e > 0.f) ? e : 0.2f * e;
    }
    __syncthreads();

    if (tid < NPG) {
        int s0 = startS[tid], s1 = startS[tid+1];
        float m = -3.0e38f;
        for (int j = s0; j < s1; j++) m = fmaxf(m, eV[order[j]]);
        float dd = 0.f;
        for (int j = s0; j < s1; j++) { int i = order[j]; float w = expf(eV[i] - m); eV[i] = w; dd += w; }
        den[tid] = dd;
    }
    __syncthreads();

    size_t fb = (size_t)g*KPAD + resOff;
    if (Fo % 4 == 0) {
        for (int t = tid; t < NPG*(Fo/4); t += 256) {
            int d = t / (Fo/4), c4 = (t % (Fo/4)) * 4;
            int s0 = startS[d], s1 = startS[d+1];
            float4 acc = make_float4(0.f,0.f,0.f,0.f);
            for (int j = s0; j < s1; j++) {
                int i = order[j]; float w = eV[i];
                const float4 h = *(const float4*)&hB[(int)esrc[i]*Fo + c4];
                acc.x = fmaf(w, h.x, acc.x); acc.y = fmaf(w, h.y, acc.y);
                acc.z = fmaf(w, h.z, acc.z); acc.w = fmaf(w, h.w, acc.w);
            }
            float inv = 1.0f / (den[d] + 1e-16f);
            float o0 = fmaxf(acc.x*inv + biasS[c4+0], 0.f);
            float o1 = fmaxf(acc.y*inv + biasS[c4+1], 0.f);
            float o2 = fmaxf(acc.z*inv + biasS[c4+2], 0.f);
            float o3 = fmaxf(acc.w*inv + biasS[c4+3], 0.f);
            hA[d*Fo+c4+0]=o0; hA[d*Fo+c4+1]=o1; hA[d*Fo+c4+2]=o2; hA[d*Fo+c4+3]=o3;
            put2(fh, fl, fb + d*Fo + c4+0, o0); put2(fh, fl, fb + d*Fo + c4+1, o1);
            put2(fh, fl, fb + d*Fo + c4+2, o2); put2(fh, fl, fb + d*Fo + c4+3, o3);
        }
    } else {
        for (int t = tid; t < NPG*Fo; t += 256) {
            int d = t / Fo, c = t % Fo;
            int s0 = startS[d], s1 = startS[d+1];
            float acc = 0.f;
            for (int j = s0; j < s1; j++) { int i = order[j]; acc = fmaf(eV[i], hB[(int)esrc[i]*Fo + c], acc); }
            float o = fmaxf(acc / (den[d] + 1e-16f) + biasS[c], 0.f);
            hA[d*Fo + c] = o;
            put2(fh, fl, fb + d*Fo + c, o);
        }
    }
    __syncthreads();

    if (tid < Fo) {
        float m = hA[tid];
        for (int n = 1; n < NPG; n++) m = fmaxf(m, hA[n*Fo + tid]);
        put2(fh, fl, (size_t)g*KPAD + poolOff + tid, m);
    }
    __syncthreads();
}

__global__ __launch_bounds__(256) void gat_kernel(
    const float* __restrict__ x, const void* __restrict__ edges,
    const float* __restrict__ W1, const float* __restrict__ as1, const float* __restrict__ ad1, const float* __restrict__ b1,
    const float* __restrict__ W2, const float* __restrict__ as2, const float* __restrict__ ad2, const float* __restrict__ b2,
    const float* __restrict__ W3, const float* __restrict__ as3, const float* __restrict__ ad3, const float* __restrict__ b3,
    const float* __restrict__ W4, const float* __restrict__ as4, const float* __restrict__ ad4, const float* __restrict__ b4,
    __nv_bfloat16* __restrict__ fh, __nv_bfloat16* __restrict__ fl)
{
    __shared__ float hA[NPG*64];
    __shared__ float hB[NPG*64];
    __shared__ float wS[64*32];
    __shared__ float aSs[64], aDs[64], biasS[64];
    __shared__ float sN[NPG], dN[NPG], den[NPG];
    __shared__ float eV[TE];
    __shared__ unsigned char  esrc[TE], edst[TE];
    __shared__ unsigned short order[TE];
    __shared__ int startS[NPG+1];
    __shared__ int cnt[NPG];

    const int g   = blockIdx.x;
    const int tid = threadIdx.x;
    const int is64 = g_is64;
    const long ebase = (long)g * EPG;

    if (tid < NPG) {
        float v = x[g*NPG + tid];
        hA[tid] = v;
        put2(fh, fl, (size_t)g*KPAD + tid, v);
    }
    for (int i = tid; i < EPG; i += 256) {
        int s, d;
        if (is64) {
            const long long* e = (const long long*)edges;
            s = (int)e[ebase + i]; d = (int)e[(long)E_TOT + ebase + i];
        } else {
            const int* e = (const int*)edges;
            s = e[ebase + i]; d = e[(long)E_TOT + ebase + i];
        }
        esrc[i] = (unsigned char)(s - g*NPG);
        edst[i] = (unsigned char)(d - g*NPG);
    }
    for (int i = EPG + tid; i < TE; i += 256) { esrc[i] = edst[i] = (unsigned char)(i - EPG); }
    if (tid < NPG) cnt[tid] = 0;
    __syncthreads();

    if (tid == 0) {
        float m = hA[0];
        for (int n = 1; n < NPG; n++) m = fmaxf(m, hA[n]);
        put2(fh, fl, (size_t)g*KPAD + 4446, m);
    }
    for (int i = tid; i < TE; i += 256) atomicAdd(&cnt[edst[i]], 1);
    __syncthreads();
    if (tid == 0) {
        int run = 0;
        for (int d = 0; d < NPG; d++) { int c = cnt[d]; startS[d] = run; cnt[d] = run; run += c; }
        startS[NPG] = run;
    }
    __syncthreads();
    for (int i = tid; i < TE; i += 256) {
        int pos = atomicAdd(&cnt[edst[i]], 1);
        order[pos] = (unsigned short)i;
    }
    __syncthreads();

    gat_layer_dev<1, 8 >(g, tid, hA, hB, wS, aSs, aDs, biasS, sN, dN, den, eV, esrc, edst, order, startS, W1, as1, ad1, b1, fh, fl,   39, 4447);
    gat_layer_dev<8, 64>(g, tid, hA, hB, wS, aSs, aDs, biasS, sN, dN, den, eV, esrc, edst, order, startS, W2, as2, ad2, b2, fh, fl,  351, 4455);
    gat_layer_dev<64,32>(g, tid, hA, hB, wS, aSs, aDs, biasS, sN, dN, den, eV, esrc, edst, order, startS, W3, as3, ad3, b3, fh, fl, 2847, 4519);
    gat_layer_dev<32, 9>(g, tid, hA, hB, wS, aSs, aDs, biasS, sN, dN, den, eV, esrc, edst, order, startS, W4, as4, ad4, b4, fh, fl, 4095, 4551);
}

// ---------------- GEMM1: split-bf16 HMMA (mma.sync), 128x128x32 -----------
// A[8192,4608] hi/lo row-major; B = lw1^T [1024,4608] hi/lo k-contiguous.
// Warp grid 2x4, warp tile 64x32. 3 passes: AhBh + AhBl + AlBh.
// smem tile: 128 rows x 40 bf16 (80B pitch -> conflict-free ldmatrix).
#define MM_TILE_B  10240
#define MM_SMEM    (8*MM_TILE_B)   /* 81920 */
#define MM_NT      (KPAD/32)       /* 144 */

__global__ __launch_bounds__(256) void mm1_kernel(
    const __nv_bfloat16* __restrict__ Ah, const __nv_bfloat16* __restrict__ Al,
    const __nv_bfloat16* __restrict__ Bh, const __nv_bfloat16* __restrict__ Bl,
    const float* __restrict__ bias, float* __restrict__ C)
{
    extern __shared__ char sm[];
    const uint32_t sb = smem_u32(sm);
    const int tid = threadIdx.x, lane = tid & 31, w = tid >> 5;
    const int wm = w >> 2, wn = w & 3;           // 2 x 4 warps
    const int m0 = blockIdx.y * 128, n0 = blockIdx.x * 128;

    const uint32_t AH[2] = {0u, MM_TILE_B};
    const uint32_t AL[2] = {2*MM_TILE_B, 3*MM_TILE_B};
    const uint32_t BH[2] = {4*MM_TILE_B, 5*MM_TILE_B};
    const uint32_t BL[2] = {6*MM_TILE_B, 7*MM_TILE_B};

    // per-thread load pattern: 2 x 16B chunks per tile
    const int r0c = tid >> 2, q0 = tid & 3;           // chunk tid
    const int r1c = (tid + 256) >> 2, q1 = tid & 3;   // chunk tid+256 (q same: (tid+256)&3 == tid&3)

    auto loadK = [&](int t, int buf) {
        const size_t k0 = (size_t)t * 32;
        const __nv_bfloat16* gA = Ah + (size_t)m0*KPAD + k0;
        const __nv_bfloat16* gAl= Al + (size_t)m0*KPAD + k0;
        const __nv_bfloat16* gB = Bh + (size_t)n0*KPAD + k0;
        const __nv_bfloat16* gBl= Bl + (size_t)n0*KPAD + k0;
        uint32_t s0 = (uint32_t)(r0c*80 + q0*16);
        uint32_t s1 = (uint32_t)(r1c*80 + q1*16);
        size_t  g0 = (size_t)r0c*KPAD + q0*8;
        size_t  g1 = (size_t)r1c*KPAD + q1*8;
        CP_ASYNC16(sb + AH[buf] + s0, gA  + g0); CP_ASYNC16(sb + AH[buf] + s1, gA  + g1);
        CP_ASYNC16(sb + AL[buf] + s0, gAl + g0); CP_ASYNC16(sb + AL[buf] + s1, gAl + g1);
        CP_ASYNC16(sb + BH[buf] + s0, gB  + g0); CP_ASYNC16(sb + BH[buf] + s1, gB  + g1);
        CP_ASYNC16(sb + BL[buf] + s0, gBl + g0); CP_ASYNC16(sb + BL[buf] + s1, gBl + g1);
        CP_COMMIT();
    };

    float acc[4][4][4];
    #pragma unroll
    for (int i = 0; i < 4; i++)
        #pragma unroll
        for (int j = 0; j < 4; j++)
            #pragma unroll
            for (int k = 0; k < 4; k++) acc[i][j][k] = 0.f;

    loadK(0, 0);
    for (int t = 0; t < MM_NT; t++) {
        const int buf = t & 1;
        if (t + 1 < MM_NT) { loadK(t + 1, buf ^ 1); CP_WAIT(1); }
        else               { CP_WAIT(0); }
        __syncthreads();

        #pragma unroll
        for (int kk = 0; kk < 2; kk++) {
            uint32_t ah[4][4], al[4][4], bh[2][4], bl[2][4];
            #pragma unroll
            for (int mi = 0; mi < 4; mi++) {
                int row = wm*64 + mi*16 + (lane & 15);
                uint32_t off = (uint32_t)(row*80 + (kk*16 + (lane >> 4)*8)*2);
                LDSM4(ah[mi], sb + AH[buf] + off);
                LDSM4(al[mi], sb + AL[buf] + off);
            }
            #pragma unroll
            for (int ni = 0; ni < 2; ni++) {
                int nrow = wn*32 + ni*16 + (lane & 7) + ((lane >> 4) & 1)*8;
                uint32_t off = (uint32_t)(nrow*80 + (kk*16 + ((lane >> 3) & 1)*8)*2);
                LDSM4(bh[ni], sb + BH[buf] + off);
                LDSM4(bl[ni], sb + BL[buf] + off);
            }
            #pragma unroll
            for (int mi = 0; mi < 4; mi++) {
                #pragma unroll
                for (int n8 = 0; n8 < 4; n8++) {
                    uint32_t* bhp = &bh[n8 >> 1][(n8 & 1)*2];
                    uint32_t* blp = &bl[n8 >> 1][(n8 & 1)*2];
                    MMA_BF16(acc[mi][n8], ah[mi], bhp);
                    MMA_BF16(acc[mi][n8], ah[mi], blp);
                    MMA_BF16(acc[mi][n8], al[mi], bhp);
                }
            }
        }
        __syncthreads();
    }

    // epilogue: C = relu(acc + bias)
    #pragma unroll
    for (int mi = 0; mi < 4; mi++) {
        #pragma unroll
        for (int n8 = 0; n8 < 4; n8++) {
            int col = n0 + wn*32 + n8*8 + (lane & 3)*2;
            float b0 = bias[col], b1 = bias[col + 1];
            #pragma unroll
            for (int h = 0; h < 2; h++) {
                size_t row = (size_t)(m0 + wm*64 + mi*16 + (lane >> 2) + h*8);
                float2 v;
                v.x = fmaxf(acc[mi][n8][h*2+0] + b0, 0.f);
                v.y = fmaxf(acc[mi][n8][h*2+1] + b1, 0.f);
                *(float2*)&C[row*1024 + col] = v;
            }
        }
    }
}

// ---------------- tiled fp32 SGEMM (gemm2) ---------------------------------
template<int BM, int BN, int BK, int TM, int TN, bool RELU>
__global__ __launch_bounds__((BM/TM)*(BN/TN)) void sgemm_kernel(
    int M, int Nn, int K,
    const float* __restrict__ A, const float* __restrict__ B,
    const float* __restrict__ bias, float* __restrict__ C)
{
    constexpr int THREADS = (BM/TM)*(BN/TN);
    __shared__ float As[2][BK][BM];
    __shared__ float Bs[2][BK][BN];

    const int brow = blockIdx.y, bcol = blockIdx.x;
    const int tid = threadIdx.x;
    const int tx = tid % (BN/TN);
    const int ty = tid / (BN/TN);

    const float* Ab = A + (long)brow*BM*K;
    const float* Bb = B + bcol*BN;

    constexpr int A_IT = (BM*BK/4) / THREADS;
    constexpr int B_IT = (BK*BN/4) / THREADS;

    float acc[TM][TN] = {};
    float4 aReg[A_IT], bReg[B_IT];

    auto loadGlobal = [&](int kt) {
        #pragma unroll
        for (int it = 0; it < A_IT; it++) {
            int fidx = tid + it*THREADS;
            int r = fidx / (BK/4), c = (fidx % (BK/4)) * 4;
            aReg[it] = *(const float4*)&Ab[(long)r*K + kt*BK + c];
        }
        #pragma unroll
        for (int it = 0; it < B_IT; it++) {
            int fidx = tid + it*THREADS;
            int r = fidx / (BN/4), c = (fidx % (BN/4)) * 4;
            bReg[it] = *(const float4*)&Bb[(long)(kt*BK + r)*Nn + c];
        }
    };
    auto storeSmem = [&](int bufi) {
        #pragma unroll
        for (int it = 0; it < A_IT; it++) {
            int fidx = tid + it*THREADS;
            int r = fidx / (BK/4), c = (fidx % (BK/4)) * 4;
            As[bufi][c+0][r] = aReg[it].x; As[bufi][c+1][r] = aReg[it].y;
            As[bufi][c+2][r] = aReg[it].z; As[bufi][c+3][r] = aReg[it].w;
        }
        #pragma unroll
        for (int it = 0; it < B_IT; it++) {
            int fidx = tid + it*THREADS;
            int r = fidx / (BN/4), c = (fidx % (BN/4)) * 4;
            *(float4*)&Bs[bufi][r][c] = bReg[it];
        }
    };

    const int nTiles = K / BK;
    loadGlobal(0);
    storeSmem(0);
    __syncthreads();

    for (int t = 0; t < nTiles; t++) {
        int cur = t & 1;
        if (t + 1 < nTiles) loadGlobal(t + 1);
        #pragma unroll
        for (int kk = 0; kk < BK; kk++) {
            float ra[TM], rb[TN];
            #pragma unroll
            for (int i = 0; i < TM; i++) ra[i] = As[cur][kk][ty*TM + i];
            #pragma unroll
            for (int j = 0; j < TN; j++) rb[j] = Bs[cur][kk][tx*TN + j];
            #pragma unroll
            for (int i = 0; i < TM; i++)
                #pragma unroll
                for (int j = 0; j < TN; j++)
                    acc[i][j] = fmaf(ra[i], rb[j], acc[i][j]);
        }
        if (t + 1 < nTiles) storeSmem((t + 1) & 1);
        __syncthreads();
    }

    #pragma unroll
    for (int i = 0; i < TM; i++) {
        long r = (long)brow*BM + ty*TM + i;
        #pragma unroll
        for (int j = 0; j < TN; j += 4) {
            int c = bcol*BN + tx*TN + j;
            float4 v;
            v.x = acc[i][j+0] + bias[c+0];
            v.y = acc[i][j+1] + bias[c+1];
            v.z = acc[i][j+2] + bias[c+2];
            v.w = acc[i][j+3] + bias[c+3];
            if (RELU) {
                v.x = fmaxf(v.x, 0.f); v.y = fmaxf(v.y, 0.f);
                v.z = fmaxf(v.z, 0.f); v.w = fmaxf(v.w, 0.f);
            }
            *(float4*)&C[r*Nn + c] = v;
        }
    }
}

// ---------------- tiny final GEMM [8192,128]x[128,9] ----------------------
__global__ void gemm3_kernel(const float* __restrict__ A, const float* __restrict__ W,
                             const float* __restrict__ bias, float* __restrict__ C)
{
    int idx = blockIdx.x*blockDim.x + threadIdx.x;
    if (idx >= B_GR*9) return;
    int r = idx / 9, c = idx % 9;
    const float* a = A + (long)r*128;
    float acc = bias[c];
    #pragma unroll 8
    for (int k = 0; k < 128; k++) acc = fmaf(a[k], W[k*9 + c], acc);
    C[idx] = acc;
}

// ---------------- launcher -------------------------------------------------
extern "C" void kernel_launch(void* const* d_in, const int* in_sizes, int n_in,
                              void* d_out, int out_size)
{
    (void)in_sizes; (void)n_in; (void)out_size;
    __nv_bfloat16 *fh, *fl, *bth, *btl;
    float *h1, *h2;
    cudaGetSymbolAddress((void**)&fh,  g_fh);
    cudaGetSymbolAddress((void**)&fl,  g_fl);
    cudaGetSymbolAddress((void**)&bth, g_bth);
    cudaGetSymbolAddress((void**)&btl, g_btl);
    cudaGetSymbolAddress((void**)&h1,  g_h1);
    cudaGetSymbolAddress((void**)&h2,  g_h2);

    cudaFuncSetAttribute(mm1_kernel, cudaFuncAttributeMaxDynamicSharedMemorySize, MM_SMEM);

    detect_kernel<<<1, 128>>>((const unsigned*)d_in[1]);

    // lw1 -> transposed hi/lo bf16
    tsplit_kernel<<<dim3(1024/32, (FDIM + 31)/32), dim3(32, 8)>>>(
        (const float*)d_in[19], bth, btl);

    gat_kernel<<<B_GR, 256>>>(
        (const float*)d_in[0], d_in[1],
        (const float*)d_in[3],  (const float*)d_in[4],  (const float*)d_in[5],  (const float*)d_in[6],
        (const float*)d_in[7],  (const float*)d_in[8],  (const float*)d_in[9],  (const float*)d_in[10],
        (const float*)d_in[11], (const float*)d_in[12], (const float*)d_in[13], (const float*)d_in[14],
        (const float*)d_in[15], (const float*)d_in[16], (const float*)d_in[17], (const float*)d_in[18],
        fh, fl);

    // GEMM1 on tensor cores (HMMA split-bf16): h1 = relu(f @ lw1 + lb1)
    mm1_kernel<<<dim3(1024/128, B_GR/128), 256, MM_SMEM>>>(
        fh, fl, bth, btl, (const float*)d_in[20], h1);

    // GEMM2: h2 = relu(h1 @ lw2 + lb2)
    sgemm_kernel<64,64,16,4,4,true><<<dim3(128/64, B_GR/64), 256>>>(
        B_GR, 128, 1024, h1, (const float*)d_in[21], (const float*)d_in[22], h2);

    // GEMM3: out = h2 @ lw3 + lb3
    gemm3_kernel<<<(B_GR*9 + 255)/256, 256>>>(
        h2, (const float*)d_in[23], (const float*)d_in[24], (float*)d_out);
}

// round 13
// speedup vs baseline: 2.6791x; 1.4115x over previous
#include <cuda_runtime.h>
#include <cuda_bf16.h>
#include <cstdint>

#define B_GR   8192
#define NPG    39
#define N_TOT  (B_GR*NPG)
#define DEG    8
#define EPG    (NPG*DEG)          /* 312 */
#define E_TOT  (N_TOT*DEG)        /* 2555904 */
#define TE     (EPG+NPG)          /* 351 */
#define FDIM   4560
#define KPAD   4608

// ---------------- scratch (static device globals, zero-initialized) -------
__device__ __align__(256) __nv_bfloat16 g_fh [(size_t)B_GR*KPAD];
__device__ __align__(256) __nv_bfloat16 g_fl [(size_t)B_GR*KPAD];
__device__ __align__(256) __nv_bfloat16 g_bth[(size_t)1024*KPAD];
__device__ __align__(256) __nv_bfloat16 g_btl[(size_t)1024*KPAD];
__device__ __align__(256) float g_h1[(size_t)B_GR*1024];
__device__ __align__(256) float g_h2[(size_t)B_GR*128];
__device__ __align__(256) float g_ha[(size_t)N_TOT*64];
__device__ __align__(256) float g_hb[(size_t)N_TOT*64];
__device__ __align__(256) float g_sn[N_TOT];
__device__ __align__(256) float g_dn[N_TOT];
__device__ __align__(256) unsigned char  g_csrc[(size_t)B_GR*352];
__device__ __align__(256) unsigned char  g_cdst[(size_t)B_GR*352];
__device__ __align__(256) unsigned short g_cstart[(size_t)B_GR*40];
__device__ int   g_is64;

// ---------------- PTX helpers (baseline sm_80-class only) ------------------
__device__ __forceinline__ uint32_t smem_u32(const void* p) {
    uint32_t a;
    asm("{ .reg .u64 t; cvta.to.shared.u64 t, %1; cvt.u32.u64 %0, t; }" : "=r"(a) : "l"(p));
    return a;
}
#define CP_ASYNC16(sa, ga) \
    asm volatile("cp.async.cg.shared.global [%0], [%1], 16;" :: "r"(sa), "l"(ga))
#define CP_COMMIT()  asm volatile("cp.async.commit_group;" ::: "memory")
#define CP_WAIT(n)   asm volatile("cp.async.wait_group %0;" :: "n"(n) : "memory")

#define LDSM4(r, addr) \
    asm volatile("ldmatrix.sync.aligned.m8n8.x4.shared.b16 {%0,%1,%2,%3}, [%4];" \
        : "=r"((r)[0]), "=r"((r)[1]), "=r"((r)[2]), "=r"((r)[3]) : "r"(addr))

#define MMA_BF16(acc, a, b) \
    asm volatile("mma.sync.aligned.m16n8k16.row.col.f32.bf16.bf16.f32 " \
        "{%0,%1,%2,%3}, {%4,%5,%6,%7}, {%8,%9}, {%0,%1,%2,%3};" \
        : "+f"((acc)[0]), "+f"((acc)[1]), "+f"((acc)[2]), "+f"((acc)[3]) \
        : "r"((a)[0]), "r"((a)[1]), "r"((a)[2]), "r"((a)[3]), \
          "r"((b)[0]), "r"((b)[1]))

__device__ __forceinline__ void put2(__nv_bfloat16* fh, __nv_bfloat16* fl, size_t idx, float v) {
    __nv_bfloat16 h = __float2bfloat16(v);
    fh[idx] = h;
    fl[idx] = __float2bfloat16(v - __bfloat162float(h));
}

// ---------------- edge dtype detection ------------------------------------
__global__ void detect_kernel(const unsigned* __restrict__ e) {
    int any = __syncthreads_or(e[2*threadIdx.x + 1] != 0u);
    if (threadIdx.x == 0) g_is64 = any ? 0 : 1;
}

// ---------------- transpose + split lw1 ------------------------------------
__global__ __launch_bounds__(256) void tsplit_kernel(const float* __restrict__ W,
                                                     __nv_bfloat16* __restrict__ bh,
                                                     __nv_bfloat16* __restrict__ bl) {
    __shared__ __align__(16) float tile[32][33];
    int kb = blockIdx.y * 32, nb = blockIdx.x * 32;
    int tx = threadIdx.x, ty = threadIdx.y;
    for (int i = ty; i < 32; i += 8) {
        int k = kb + i;
        tile[i][tx] = (k < FDIM) ? W[(size_t)k*1024 + nb + tx] : 0.f;
    }
    __syncthreads();
    for (int i = ty; i < 32; i += 8) {
        int n = nb + i, k = kb + tx;
        if (k < FDIM) put2(bh, bl, (size_t)n*KPAD + k, tile[tx][i]);
    }
}

// ---------------- prep: CSR build (deterministic) + res0/pool0 -------------
__global__ __launch_bounds__(64) void prep_kernel(
    const float* __restrict__ x, const void* __restrict__ edges,
    unsigned char* __restrict__ csrc, unsigned char* __restrict__ cdst,
    unsigned short* __restrict__ cstart,
    __nv_bfloat16* __restrict__ fh, __nv_bfloat16* __restrict__ fl)
{
    __shared__ __align__(16) unsigned char es[TE], ed[TE];
    __shared__ __align__(16) int cnt[NPG];
    __shared__ __align__(16) unsigned short st[NPG+1];
    const int g = blockIdx.x, tid = threadIdx.x;
    const int is64 = g_is64;
    const long ebase = (long)g*EPG;
    if (tid < NPG) cnt[tid] = 0;
    for (int i = tid; i < EPG; i += 64) {
        int s, d;
        if (is64) { const long long* e=(const long long*)edges; s=(int)e[ebase+i]; d=(int)e[(long)E_TOT+ebase+i]; }
        else      { const int* e=(const int*)edges; s=e[ebase+i]; d=e[(long)E_TOT+ebase+i]; }
        es[i]=(unsigned char)(s-g*NPG); ed[i]=(unsigned char)(d-g*NPG);
    }
    for (int i = EPG+tid; i < TE; i += 64) { es[i]=ed[i]=(unsigned char)(i-EPG); }
    __syncthreads();
    for (int i = tid; i < TE; i += 64) atomicAdd(&cnt[ed[i]], 1);
    __syncthreads();
    if (tid == 0) {
        int run = 0;
        for (int d = 0; d < NPG; d++) { st[d]=(unsigned short)run; run += cnt[d]; }
        st[NPG] = (unsigned short)run;
    }
    __syncthreads();
    if (tid < NPG) {                     // deterministic scatter per dst
        int pos = st[tid];
        for (int i = 0; i < TE; i++)
            if (ed[i] == (unsigned char)tid) {
                csrc[(size_t)g*352 + pos] = es[i];
                cdst[(size_t)g*352 + pos] = (unsigned char)tid;
                pos++;
            }
    }
    if (tid < NPG+1) cstart[(size_t)g*40 + tid] = st[tid];
    if (tid < NPG)   put2(fh, fl, (size_t)g*KPAD + tid, x[g*NPG + tid]);
    if (tid == 0) {
        float m = x[g*NPG];
        for (int n = 1; n < NPG; n++) m = fmaxf(m, x[g*NPG + n]);
        put2(fh, fl, (size_t)g*KPAD + 4446, m);
    }
}

// ---------------- layer A: dense H = hprev @ W, s/d logits -----------------
template<int Fi, int Fo>
__global__ __launch_bounds__(256) void layerA_kernel(
    const float* __restrict__ hprev, const float* __restrict__ W,
    const float* __restrict__ a_s, const float* __restrict__ a_d,
    float* __restrict__ H, float* __restrict__ sN, float* __restrict__ dN)
{
    constexpr int NB = 128;
    __shared__ __align__(16) float wS[Fi*Fo];
    __shared__ __align__(16) float asS[Fo];
    __shared__ __align__(16) float adS[Fo];
    __shared__ __align__(16) float xS[NB*Fi];
    __shared__ __align__(16) float htmp[(Fo % 4 == 0) ? 4 : NB*Fo];
    const int tid = threadIdx.x;
    const size_t n0 = (size_t)blockIdx.x * NB;

    for (int i = tid; i < Fi*Fo; i += 256) wS[i] = W[i];
    if (tid < Fo) { asS[tid] = a_s[tid]; adS[tid] = a_d[tid]; }
    for (int i = tid; i < NB*Fi/4; i += 256)
        *(float4*)&xS[i*4] = *(const float4*)&hprev[n0*Fi + i*4];
    __syncthreads();

    if constexpr (Fo % 4 == 0) {
        constexpr int C4 = Fo/4;          // 2, 16, 8 — all powers of 2
        const int lane = tid & 31;
        for (int it = tid; it < NB*C4; it += 256) {
            int n = it / C4, c4 = (it % C4)*4;
            float4 acc = make_float4(0.f,0.f,0.f,0.f);
            #pragma unroll
            for (int ci = 0; ci < Fi; ci++) {
                float a = xS[n*Fi + ci];
                const float4 w = *(const float4*)&wS[ci*Fo + c4];
                acc.x=fmaf(a,w.x,acc.x); acc.y=fmaf(a,w.y,acc.y);
                acc.z=fmaf(a,w.z,acc.z); acc.w=fmaf(a,w.w,acc.w);
            }
            *(float4*)&H[(n0+n)*Fo + c4] = acc;
            float sp = acc.x*asS[c4] + acc.y*asS[c4+1] + acc.z*asS[c4+2] + acc.w*asS[c4+3];
            float dp = acc.x*adS[c4] + acc.y*adS[c4+1] + acc.z*adS[c4+2] + acc.w*adS[c4+3];
            #pragma unroll
            for (int off = C4/2; off > 0; off >>= 1) {
                sp += __shfl_xor_sync(0xffffffffu, sp, off);
                dp += __shfl_xor_sync(0xffffffffu, dp, off);
            }
            if ((lane & (C4-1)) == 0) { sN[n0+n] = sp; dN[n0+n] = dp; }
        }
    } else {
        for (int it = tid; it < NB*Fo; it += 256) {
            int n = it / Fo, c = it % Fo;
            float acc = 0.f;
            #pragma unroll
            for (int ci = 0; ci < Fi; ci++) acc = fmaf(xS[n*Fi+ci], wS[ci*Fo+c], acc);
            H[(n0+n)*Fo + c] = acc;
            htmp[n*Fo + c] = acc;
        }
        __syncthreads();
        if (tid < NB) {
            float s = 0.f, d = 0.f;
            #pragma unroll
            for (int c = 0; c < Fo; c++) { float v = htmp[tid*Fo+c]; s = fmaf(v, asS[c], s); d = fmaf(v, adS[c], d); }
            sN[n0+tid] = s; dN[n0+tid] = d;
        }
    }
}

// ---------------- layer B: per-graph softmax + aggregate -------------------
template<int Fo, bool HNEXT>
__global__ __launch_bounds__(128) void layerB_kernel(
    const float* __restrict__ H, const float* __restrict__ sN, const float* __restrict__ dN,
    const unsigned char* __restrict__ csrc, const unsigned char* __restrict__ cdst,
    const unsigned short* __restrict__ cstart,
    const float* __restrict__ bvec, float* __restrict__ hnext,
    __nv_bfloat16* __restrict__ fh, __nv_bfloat16* __restrict__ fl,
    int resOff, int poolOff)
{
    __shared__ __align__(16) float hS[NPG*Fo];
    __shared__ __align__(16) float oS[NPG*Fo];
    __shared__ __align__(16) float eW[TE];
    __shared__ __align__(16) float snS[NPG];
    __shared__ __align__(16) float dnS[NPG];
    __shared__ __align__(16) float denS[NPG];
    __shared__ __align__(16) float biasS[Fo];
    __shared__ __align__(16) unsigned char srcS[TE];
    __shared__ __align__(16) unsigned char dstS[TE];
    __shared__ __align__(16) unsigned short stS[NPG+1];
    const int tid = threadIdx.x;
    const int g = blockIdx.x;
    const size_t nb = (size_t)g * NPG;

    if constexpr (Fo % 4 == 0) {
        for (int i = tid; i < NPG*Fo/4; i += 128)
            *(float4*)&hS[i*4] = *(const float4*)&H[nb*Fo + i*4];
    } else {
        for (int i = tid; i < NPG*Fo; i += 128) hS[i] = H[nb*Fo + i];
    }
    if (tid < NPG)   { snS[tid] = sN[nb+tid]; dnS[tid] = dN[nb+tid]; }
    if (tid < Fo)    biasS[tid] = bvec[tid];
    if (tid < NPG+1) stS[tid] = cstart[(size_t)g*40 + tid];
    for (int i = tid; i < TE; i += 128) {
        srcS[i] = csrc[(size_t)g*352 + i];
        dstS[i] = cdst[(size_t)g*352 + i];
    }
    __syncthreads();

    for (int i = tid; i < TE; i += 128) {
        float e = snS[srcS[i]] + dnS[dstS[i]];
        eW[i] = e > 0.f ? e : 0.2f*e;
    }
    __syncthreads();

    if (tid < NPG) {
        int s0 = stS[tid], s1 = stS[tid+1];
        float m = -3.0e38f;
        for (int j = s0; j < s1; j++) m = fmaxf(m, eW[j]);
        float dd = 0.f;
        for (int j = s0; j < s1; j++) { float w = __expf(eW[j] - m); eW[j] = w; dd += w; }
        denS[tid] = dd;
    }
    __syncthreads();

    const size_t fbase = (size_t)g*KPAD + resOff;
    if constexpr (Fo % 4 == 0) {
        constexpr int C4 = Fo/4;
        for (int it = tid; it < NPG*C4; it += 128) {
            int d = it / C4, c4 = (it % C4)*4;
            int s0 = stS[d], s1 = stS[d+1];
            float4 acc = make_float4(0.f,0.f,0.f,0.f);
            for (int j = s0; j < s1; j++) {
                float w = eW[j];
                const float4 h = *(const float4*)&hS[(int)srcS[j]*Fo + c4];
                acc.x=fmaf(w,h.x,acc.x); acc.y=fmaf(w,h.y,acc.y);
                acc.z=fmaf(w,h.z,acc.z); acc.w=fmaf(w,h.w,acc.w);
            }
            float inv = 1.0f/(denS[d] + 1e-16f);
            float o0 = fmaxf(acc.x*inv + biasS[c4+0], 0.f);
            float o1 = fmaxf(acc.y*inv + biasS[c4+1], 0.f);
            float o2 = fmaxf(acc.z*inv + biasS[c4+2], 0.f);
            float o3 = fmaxf(acc.w*inv + biasS[c4+3], 0.f);
            oS[d*Fo+c4+0]=o0; oS[d*Fo+c4+1]=o1; oS[d*Fo+c4+2]=o2; oS[d*Fo+c4+3]=o3;
            size_t fb = fbase + d*Fo + c4;
            put2(fh,fl,fb+0,o0); put2(fh,fl,fb+1,o1); put2(fh,fl,fb+2,o2); put2(fh,fl,fb+3,o3);
            if (HNEXT) *(float4*)&hnext[(nb+d)*Fo + c4] = make_float4(o0,o1,o2,o3);
        }
    } else {
        for (int it = tid; it < NPG*Fo; it += 128) {
            int d = it / Fo, c = it % Fo;
            int s0 = stS[d], s1 = stS[d+1];
            float acc = 0.f;
            for (int j = s0; j < s1; j++) acc = fmaf(eW[j], hS[(int)srcS[j]*Fo + c], acc);
            float o = fmaxf(acc/(denS[d]+1e-16f) + biasS[c], 0.f);
            oS[d*Fo + c] = o;
            put2(fh, fl, fbase + d*Fo + c, o);
            if (HNEXT) hnext[(nb+d)*Fo + c] = o;
        }
    }
    __syncthreads();
    if (tid < Fo) {
        float m = oS[tid];
        for (int n = 1; n < NPG; n++) m = fmaxf(m, oS[n*Fo + tid]);
        put2(fh, fl, (size_t)g*KPAD + poolOff + tid, m);
    }
}

// ---------------- GEMM1: split-bf16 HMMA, 4-stage cp.async ring ------------
#define MM_TILE_B  10240
#define MM_STAGE_B (4*MM_TILE_B)       /* 40960 */
#define MM_SMEM    (4*MM_STAGE_B)      /* 163840 */
#define MM_NT      (KPAD/32)           /* 144 */

__global__ __launch_bounds__(256) void mm1_kernel(
    const __nv_bfloat16* __restrict__ Ah, const __nv_bfloat16* __restrict__ Al,
    const __nv_bfloat16* __restrict__ Bh, const __nv_bfloat16* __restrict__ Bl,
    const float* __restrict__ bias, float* __restrict__ C)
{
    extern __shared__ __align__(128) char sm[];
    const uint32_t sb = smem_u32(sm);
    const int tid = threadIdx.x, lane = tid & 31, w = tid >> 5;
    const int wm = w >> 2, wn = w & 3;
    const int m0 = blockIdx.y * 128, n0 = blockIdx.x * 128;

    const int r0c = tid >> 2, q0 = tid & 3;
    const int r1c = (tid + 256) >> 2, q1 = tid & 3;

    auto loadK = [&](int t, int st) {
        const uint32_t base = sb + st*MM_STAGE_B;
        const size_t k0 = (size_t)t * 32;
        const __nv_bfloat16* gA  = Ah + (size_t)m0*KPAD + k0;
        const __nv_bfloat16* gAl = Al + (size_t)m0*KPAD + k0;
        const __nv_bfloat16* gB  = Bh + (size_t)n0*KPAD + k0;
        const __nv_bfloat16* gBl = Bl + (size_t)n0*KPAD + k0;
        uint32_t s0 = (uint32_t)(r0c*80 + q0*16);
        uint32_t s1 = (uint32_t)(r1c*80 + q1*16);
        size_t  g0 = (size_t)r0c*KPAD + q0*8;
        size_t  g1 = (size_t)r1c*KPAD + q1*8;
        CP_ASYNC16(base + 0*MM_TILE_B + s0, gA  + g0); CP_ASYNC16(base + 0*MM_TILE_B + s1, gA  + g1);
        CP_ASYNC16(base + 1*MM_TILE_B + s0, gAl + g0); CP_ASYNC16(base + 1*MM_TILE_B + s1, gAl + g1);
        CP_ASYNC16(base + 2*MM_TILE_B + s0, gB  + g0); CP_ASYNC16(base + 2*MM_TILE_B + s1, gB  + g1);
        CP_ASYNC16(base + 3*MM_TILE_B + s0, gBl + g0); CP_ASYNC16(base + 3*MM_TILE_B + s1, gBl + g1);
        CP_COMMIT();
    };

    float acc[4][4][4];
    #pragma unroll
    for (int i = 0; i < 4; i++)
        #pragma unroll
        for (int j = 0; j < 4; j++)
            #pragma unroll
            for (int k = 0; k < 4; k++) acc[i][j][k] = 0.f;

    loadK(0, 0); loadK(1, 1); loadK(2, 2);

    for (int t = 0; t < MM_NT; t++) {
        const int st = t & 3;
        const uint32_t base = sb + st*MM_STAGE_B;
        CP_WAIT(2);
        __syncthreads();

        #pragma unroll
        for (int kk = 0; kk < 2; kk++) {
            uint32_t ah[4][4], al[4][4], bh[2][4], bl[2][4];
            #pragma unroll
            for (int mi = 0; mi < 4; mi++) {
                int row = wm*64 + mi*16 + (lane & 15);
                uint32_t off = (uint32_t)(row*80 + (kk*16 + (lane >> 4)*8)*2);
                LDSM4(ah[mi], base + 0*MM_TILE_B + off);
                LDSM4(al[mi], base + 1*MM_TILE_B + off);
            }
            #pragma unroll
            for (int ni = 0; ni < 2; ni++) {
                int nrow = wn*32 + ni*16 + (lane & 7) + ((lane >> 4) & 1)*8;
                uint32_t off = (uint32_t)(nrow*80 + (kk*16 + ((lane >> 3) & 1)*8)*2);
                LDSM4(bh[ni], base + 2*MM_TILE_B + off);
                LDSM4(bl[ni], base + 3*MM_TILE_B + off);
            }
            #pragma unroll
            for (int mi = 0; mi < 4; mi++) {
                #pragma unroll
                for (int n8 = 0; n8 < 4; n8++) {
                    uint32_t* bhp = &bh[n8 >> 1][(n8 & 1)*2];
                    uint32_t* blp = &bl[n8 >> 1][(n8 & 1)*2];
                    MMA_BF16(acc[mi][n8], ah[mi], bhp);
                    MMA_BF16(acc[mi][n8], ah[mi], blp);
                    MMA_BF16(acc[mi][n8], al[mi], bhp);
                }
            }
        }
        if (t + 3 < MM_NT) loadK(t + 3, (t + 3) & 3);
    }

    #pragma unroll
    for (int mi = 0; mi < 4; mi++) {
        #pragma unroll
        for (int n8 = 0; n8 < 4; n8++) {
            int col = n0 + wn*32 + n8*8 + (lane & 3)*2;
            float b0 = bias[col], b1 = bias[col + 1];
            #pragma unroll
            for (int h = 0; h < 2; h++) {
                size_t row = (size_t)(m0 + wm*64 + mi*16 + (lane >> 2) + h*8);
                float2 v;
                v.x = fmaxf(acc[mi][n8][h*2+0] + b0, 0.f);
                v.y = fmaxf(acc[mi][n8][h*2+1] + b1, 0.f);
                *(float2*)&C[row*1024 + col] = v;
            }
        }
    }
}

// ---------------- tiled fp32 SGEMM (gemm2) ---------------------------------
template<int BM, int BN, int BK, int TM, int TN, bool RELU>
__global__ __launch_bounds__((BM/TM)*(BN/TN)) void sgemm_kernel(
    int M, int Nn, int K,
    const float* __restrict__ A, const float* __restrict__ B,
    const float* __restrict__ bias, float* __restrict__ C)
{
    constexpr int THREADS = (BM/TM)*(BN/TN);
    __shared__ __align__(16) float As[2][BK][BM];
    __shared__ __align__(16) float Bs[2][BK][BN];

    const int brow = blockIdx.y, bcol = blockIdx.x;
    const int tid = threadIdx.x;
    const int tx = tid % (BN/TN);
    const int ty = tid / (BN/TN);

    const float* Ab = A + (long)brow*BM*K;
    const float* Bb = B + bcol*BN;

    constexpr int A_IT = (BM*BK/4) / THREADS;
    constexpr int B_IT = (BK*BN/4) / THREADS;

    float acc[TM][TN] = {};
    float4 aReg[A_IT], bReg[B_IT];

    auto loadGlobal = [&](int kt) {
        #pragma unroll
        for (int it = 0; it < A_IT; it++) {
            int fidx = tid + it*THREADS;
            int r = fidx / (BK/4), c = (fidx % (BK/4)) * 4;
            aReg[it] = *(const float4*)&Ab[(long)r*K + kt*BK + c];
        }
        #pragma unroll
        for (int it = 0; it < B_IT; it++) {
            int fidx = tid + it*THREADS;
            int r = fidx / (BN/4), c = (fidx % (BN/4)) * 4;
            bReg[it] = *(const float4*)&Bb[(long)(kt*BK + r)*Nn + c];
        }
    };
    auto storeSmem = [&](int bufi) {
        #pragma unroll
        for (int it = 0; it < A_IT; it++) {
            int fidx = tid + it*THREADS;
            int r = fidx / (BK/4), c = (fidx % (BK/4)) * 4;
            As[bufi][c+0][r] = aReg[it].x; As[bufi][c+1][r] = aReg[it].y;
            As[bufi][c+2][r] = aReg[it].z; As[bufi][c+3][r] = aReg[it].w;
        }
        #pragma unroll
        for (int it = 0; it < B_IT; it++) {
            int fidx = tid + it*THREADS;
            int r = fidx / (BN/4), c = (fidx % (BN/4)) * 4;
            *(float4*)&Bs[bufi][r][c] = bReg[it];
        }
    };

    const int nTiles = K / BK;
    loadGlobal(0);
    storeSmem(0);
    __syncthreads();

    for (int t = 0; t < nTiles; t++) {
        int cur = t & 1;
        if (t + 1 < nTiles) loadGlobal(t + 1);
        #pragma unroll
        for (int kk = 0; kk < BK; kk++) {
            float ra[TM], rb[TN];
            #pragma unroll
            for (int i = 0; i < TM; i++) ra[i] = As[cur][kk][ty*TM + i];
            #pragma unroll
            for (int j = 0; j < TN; j++) rb[j] = Bs[cur][kk][tx*TN + j];
            #pragma unroll
            for (int i = 0; i < TM; i++)
                #pragma unroll
                for (int j = 0; j < TN; j++)
                    acc[i][j] = fmaf(ra[i], rb[j], acc[i][j]);
        }
        if (t + 1 < nTiles) storeSmem((t + 1) & 1);
        __syncthreads();
    }

    #pragma unroll
    for (int i = 0; i < TM; i++) {
        long r = (long)brow*BM + ty*TM + i;
        #pragma unroll
        for (int j = 0; j < TN; j += 4) {
            int c = bcol*BN + tx*TN + j;
            float4 v;
            v.x = acc[i][j+0] + bias[c+0];
            v.y = acc[i][j+1] + bias[c+1];
            v.z = acc[i][j+2] + bias[c+2];
            v.w = acc[i][j+3] + bias[c+3];
            if (RELU) {
                v.x = fmaxf(v.x, 0.f); v.y = fmaxf(v.y, 0.f);
                v.z = fmaxf(v.z, 0.f); v.w = fmaxf(v.w, 0.f);
            }
            *(float4*)&C[r*Nn + c] = v;
        }
    }
}

// ---------------- tiny final GEMM ------------------------------------------
__global__ void gemm3_kernel(const float* __restrict__ A, const float* __restrict__ W,
                             const float* __restrict__ bias, float* __restrict__ C)
{
    int idx = blockIdx.x*blockDim.x + threadIdx.x;
    if (idx >= B_GR*9) return;
    int r = idx / 9, c = idx % 9;
    const float* a = A + (long)r*128;
    float acc = bias[c];
    #pragma unroll 8
    for (int k = 0; k < 128; k++) acc = fmaf(a[k], W[k*9 + c], acc);
    C[idx] = acc;
}

// ---------------- launcher -------------------------------------------------
extern "C" void kernel_launch(void* const* d_in, const int* in_sizes, int n_in,
                              void* d_out, int out_size)
{
    (void)in_sizes; (void)n_in; (void)out_size;
    __nv_bfloat16 *fh, *fl, *bth, *btl;
    float *h1, *h2, *ha, *hb, *sn, *dn;
    unsigned char *csrc, *cdst;
    unsigned short *cstart;
    cudaGetSymbolAddress((void**)&fh,  g_fh);
    cudaGetSymbolAddress((void**)&fl,  g_fl);
    cudaGetSymbolAddress((void**)&bth, g_bth);
    cudaGetSymbolAddress((void**)&btl, g_btl);
    cudaGetSymbolAddress((void**)&h1,  g_h1);
    cudaGetSymbolAddress((void**)&h2,  g_h2);
    cudaGetSymbolAddress((void**)&ha,  g_ha);
    cudaGetSymbolAddress((void**)&hb,  g_hb);
    cudaGetSymbolAddress((void**)&sn,  g_sn);
    cudaGetSymbolAddress((void**)&dn,  g_dn);
    cudaGetSymbolAddress((void**)&csrc, g_csrc);
    cudaGetSymbolAddress((void**)&cdst, g_cdst);
    cudaGetSymbolAddress((void**)&cstart, g_cstart);

    cudaFuncSetAttribute(mm1_kernel, cudaFuncAttributeMaxDynamicSharedMemorySize, MM_SMEM);

    const float* x = (const float*)d_in[0];

    detect_kernel<<<1, 128>>>((const unsigned*)d_in[1]);
    prep_kernel<<<B_GR, 64>>>(x, d_in[1], csrc, cdst, cstart, fh, fl);
    tsplit_kernel<<<dim3(1024/32, (FDIM + 31)/32), dim3(32, 8)>>>(
        (const float*)d_in[19], bth, btl);

    // layer 1: 1 -> 8
    layerA_kernel<1,8><<<N_TOT/128, 256>>>(x, (const float*)d_in[3],
        (const float*)d_in[4], (const float*)d_in[5], ha, sn, dn);
    layerB_kernel<8,true><<<B_GR, 128>>>(ha, sn, dn, csrc, cdst, cstart,
        (const float*)d_in[6], hb, fh, fl, 39, 4447);
    // layer 2: 8 -> 64
    layerA_kernel<8,64><<<N_TOT/128, 256>>>(hb, (const float*)d_in[7],
        (const float*)d_in[8], (const float*)d_in[9], ha, sn, dn);
    layerB_kernel<64,true><<<B_GR, 128>>>(ha, sn, dn, csrc, cdst, cstart,
        (const float*)d_in[10], hb, fh, fl, 351, 4455);
    // layer 3: 64 -> 32
    layerA_kernel<64,32><<<N_TOT/128, 256>>>(hb, (const float*)d_in[11],
        (const float*)d_in[12], (const float*)d_in[13], ha, sn, dn);
    layerB_kernel<32,true><<<B_GR, 128>>>(ha, sn, dn, csrc, cdst, cstart,
        (const float*)d_in[14], hb, fh, fl, 2847, 4519);
    // layer 4: 32 -> 9
    layerA_kernel<32,9><<<N_TOT/128, 256>>>(hb, (const float*)d_in[15],
        (const float*)d_in[16], (const float*)d_in[17], ha, sn, dn);
    layerB_kernel<9,false><<<B_GR, 128>>>(ha, sn, dn, csrc, cdst, cstart,
        (const float*)d_in[18], hb, fh, fl, 4095, 4551);

    // GEMM1 (HMMA split-bf16): h1 = relu(f @ lw1 + lb1)
    mm1_kernel<<<dim3(1024/128, B_GR/128), 256, MM_SMEM>>>(
        fh, fl, bth, btl, (const float*)d_in[20], h1);
    // GEMM2: h2 = relu(h1 @ lw2 + lb2)
    sgemm_kernel<64,64,16,4,4,true><<<dim3(128/64, B_GR/64), 256>>>(
        B_GR, 128, 1024, h1, (const float*)d_in[21], (const float*)d_in[22], h2);
    // GEMM3: out = h2 @ lw3 + lb3
    gemm3_kernel<<<(B_GR*9 + 255)/256, 256>>>(
        h2, (const float*)d_in[23], (const float*)d_in[24], (float*)d_out);
}